// round 7
// baseline (speedup 1.0000x reference)
#include <cuda_runtime.h>
#include <cuda_bf16.h>

// Problem constants
#define CC      64      // channels
#define DI      128     // d_inner
#define DS      16      // d_state
#define LL      4096    // sequence length H*W
#define BB      4       // batch
#define NTOK    (BB*LL) // 16384 tokens
#define NCHUNK  32
#define CSIZE   128     // LL / NCHUNK

// ---------------- scratch (device globals; no allocation allowed) ------------
__device__ __align__(16) float g_hn   [NTOK*CC];   // LayerNorm output [m, c]
__device__ __align__(16) float g_seqT [BB*CC*LL];  // pre-LN activations [b,c,l]
__device__ __align__(16) float g_xm   [NTOK*DI];   // in_proj first half [m, d]
__device__ __align__(16) float g_z    [NTOK*DI];   // in_proj second half [m, d]
__device__ __align__(16) float g_xc   [NTOK*DI];   // conv1d+silu output [m, d]
__device__ __align__(16) float g_dt   [NTOK*DI];   // softplus(dt) [m, d]
__device__ __align__(16) float g_Bm   [NTOK*DS];   // [m, s]
__device__ __align__(16) float g_Cm   [NTOK*DS];   // [m, s]
__device__ __align__(16) float g_dtr  [NTOK*4];    // dt-rank dots [m, r]
__device__ __align__(16) float g_ysT  [BB*DI*LL];  // scan output [b,d,l]
__device__ __align__(16) float g_hend [BB*NCHUNK*DI*DS];
__device__ __align__(16) float g_hinit[BB*NCHUNK*DI*DS];
__device__ __align__(16) float g_sumdt[BB*NCHUNK*DI];

// ---------------- f32x2 helpers ----------------
__device__ __forceinline__ unsigned long long pk2(float x, float y) {
    unsigned long long r;
    asm("mov.b64 %0, {%1, %2};" : "=l"(r) : "f"(x), "f"(y));
    return r;
}
__device__ __forceinline__ void upk2(unsigned long long v, float& x, float& y) {
    asm("mov.b64 {%0, %1}, %2;" : "=f"(x), "=f"(y) : "l"(v));
}
__device__ __forceinline__ unsigned long long fma2(
    unsigned long long a, unsigned long long b, unsigned long long c) {
    unsigned long long d;
    asm("fma.rn.f32x2 %0, %1, %2, %3;" : "=l"(d) : "l"(a), "l"(b), "l"(c));
    return d;
}

// ============================================================================
// K1: axial depthwise convs + 1x1 conv + BN + ReLU + LayerNorm
// one block per (b, h) image row; 512 threads
// ============================================================================
__global__ __launch_bounds__(512) void k1_front(
    const float* __restrict__ x,
    const float* __restrict__ dwh_w, const float* __restrict__ dwh_b,
    const float* __restrict__ dww_w, const float* __restrict__ dww_b,
    const float* __restrict__ conv_w, const float* __restrict__ conv_b,
    const float* __restrict__ bn_g, const float* __restrict__ bn_b,
    const float* __restrict__ bn_m, const float* __restrict__ bn_v,
    const float* __restrict__ ln_g, const float* __restrict__ ln_b)
{
    __shared__ float sm[64][65];       // m[c][w], later t[c][w]
    __shared__ float scw[64*64];       // 1x1 conv weights
    __shared__ float red_s[64][8];
    __shared__ float red_q[64][8];
    __shared__ float s_mu[64], s_rs[64];

    int bh = blockIdx.x;               // 0..255
    int b = bh >> 6, h = bh & 63;
    int tid = threadIdx.x;

    for (int i = tid; i < 4096; i += 512) scw[i] = conv_w[i];

    for (int i = tid; i < 4096; i += 512) {
        int c = i >> 6, w = i & 63;
        const float* xb = x + ((b*64 + c)*64)*64;
        float center = xb[h*64 + w];
        float acc = center;
        float wh0 = dwh_w[c*3+0], wh1 = dwh_w[c*3+1], wh2 = dwh_w[c*3+2];
        if (h > 0)  acc += wh0 * xb[(h-1)*64 + w];
        acc += wh1 * center;
        if (h < 63) acc += wh2 * xb[(h+1)*64 + w];
        float ww0 = dww_w[c*3+0], ww1 = dww_w[c*3+1], ww2 = dww_w[c*3+2];
        if (w > 0)  acc += ww0 * xb[h*64 + w - 1];
        acc += ww1 * center;
        if (w < 63) acc += ww2 * xb[h*64 + w + 1];
        acc += dwh_b[c] + dww_b[c];
        sm[c][w] = acc;
    }
    __syncthreads();

    float t[8];
    #pragma unroll
    for (int j = 0; j < 8; j++) {
        int i = tid + j*512;
        int o = i >> 6, w = i & 63;
        float acc = 0.f;
        #pragma unroll 8
        for (int c = 0; c < 64; c++) acc += scw[o*64+c]*sm[c][w];
        acc += conv_b[o];
        float rs = rsqrtf(bn_v[o] + 1e-5f);
        acc = (acc - bn_m[o]) * rs * bn_g[o] + bn_b[o];
        t[j] = fmaxf(acc, 0.f);
    }
    __syncthreads();
    #pragma unroll
    for (int j = 0; j < 8; j++) {
        int i = tid + j*512;
        sm[i>>6][i&63] = t[j];
    }
    __syncthreads();

    {
        int w = tid & 63, p = tid >> 6;       // p in 0..7
        float s = 0.f, q = 0.f;
        #pragma unroll
        for (int c = p*8; c < p*8+8; c++) { float v = sm[c][w]; s += v; q += v*v; }
        red_s[w][p] = s; red_q[w][p] = q;
    }
    __syncthreads();
    if (tid < 64) {
        float s = 0.f, q = 0.f;
        #pragma unroll
        for (int p = 0; p < 8; p++) { s += red_s[tid][p]; q += red_q[tid][p]; }
        float mu = s * (1.f/64.f);
        float var = q * (1.f/64.f) - mu*mu;
        s_mu[tid] = mu;
        s_rs[tid] = rsqrtf(var + 1e-5f);
    }
    __syncthreads();

    int mbase = b*LL + h*64;
    for (int i = tid; i < 4096; i += 512) {
        int w = i >> 6, c = i & 63;
        float v = sm[c][w];
        g_hn[(mbase + w)*64 + c] = (v - s_mu[w]) * s_rs[w] * ln_g[c] + ln_b[c];
    }
    for (int i = tid; i < 4096; i += 512) {
        int c = i >> 6, w = i & 63;
        g_seqT[(b*64 + c)*LL + h*64 + w] = sm[c][w];
    }
}

// ============================================================================
// K2: in_proj GEMM via fma.rn.f32x2 (token pairs packed).
// Tile 64 tok x 64 out; thread = (o0 0..15, t0 0..15); pairs {u, u+32}.
// ============================================================================
__global__ __launch_bounds__(256) void k2_inproj(const float* __restrict__ W)
{
    __shared__ unsigned long long sa2[32*64];  // [pair u][k] = (hn[u], hn[u+32])
    __shared__ float sw[64][65];               // weight tile [o][k]
    int m0 = blockIdx.x * 64;
    int n0 = blockIdx.y * 64;
    int tid = threadIdx.x;

    for (int i = tid; i < 2048; i += 256) {
        int u = i >> 6, kk = i & 63;
        float a0 = g_hn[(m0+u)*64 + kk];
        float a1 = g_hn[(m0+u+32)*64 + kk];
        sa2[u*64 + kk] = pk2(a0, a1);
    }
    for (int i = tid; i < 4096; i += 256) {
        int r = i >> 6, kk = i & 63;
        sw[r][kk] = W[(n0+r)*64 + kk];
    }
    __syncthreads();

    int o0 = tid & 15;
    int t0 = tid >> 4;
    unsigned long long acc2[2][4];
    #pragma unroll
    for (int a = 0; a < 2; a++)
        #pragma unroll
        for (int bb = 0; bb < 4; bb++) acc2[a][bb] = 0ULL;

    #pragma unroll 4
    for (int k = 0; k < 64; k++) {
        unsigned long long av0 = sa2[t0*64 + k];
        unsigned long long av1 = sa2[(t0+16)*64 + k];
        #pragma unroll
        for (int bb = 0; bb < 4; bb++) {
            float w = sw[o0 + 16*bb][k];
            unsigned long long w2 = pk2(w, w);
            acc2[0][bb] = fma2(av0, w2, acc2[0][bb]);
            acc2[1][bb] = fma2(av1, w2, acc2[1][bb]);
        }
    }

    #pragma unroll
    for (int a = 0; a < 2; a++) {
        int mlo = m0 + t0 + 16*a;        // pair = {mlo, mlo+32}
        #pragma unroll
        for (int bb = 0; bb < 4; bb++) {
            float lo, hi; upk2(acc2[a][bb], lo, hi);
            int og = n0 + o0 + 16*bb;
            if (og < 128) {
                g_xm[mlo*128 + og]      = lo;
                g_xm[(mlo+32)*128 + og] = hi;
            } else {
                g_z[mlo*128 + og - 128]      = lo;
                g_z[(mlo+32)*128 + og - 128] = hi;
            }
        }
    }
}

// ============================================================================
// K3: causal depthwise conv1d (k=4) + SiLU, float4 over d
// ============================================================================
__global__ __launch_bounds__(256) void k3_conv1d(
    const float* __restrict__ cw, const float* __restrict__ cb)
{
    int i = blockIdx.x*256 + threadIdx.x;      // over NTOK*32 float4s
    int q = i & 31;            // float4 index within 128 channels
    int m = i >> 5;
    int l = m & (LL-1);
    const float4* xm4 = (const float4*)g_xm;
    const float4* cw4 = (const float4*)cw;     // cw4[d] = 4 taps of channel d
    const float4* cb4 = (const float4*)cb;
    float4 zero = make_float4(0.f,0.f,0.f,0.f);
    float4 cur = xm4[i];
    float4 p1 = (l >= 1) ? xm4[i-32] : zero;
    float4 p2 = (l >= 2) ? xm4[i-64] : zero;
    float4 p3 = (l >= 3) ? xm4[i-96] : zero;
    float4 bias = cb4[q];
    int d0 = q*4;
    float4 r;
    {
        float4 w = cw4[d0+0];
        float a = bias.x + w.w*cur.x + w.z*p1.x + w.y*p2.x + w.x*p3.x;
        r.x = a / (1.f + __expf(-a));
    }
    {
        float4 w = cw4[d0+1];
        float a = bias.y + w.w*cur.y + w.z*p1.y + w.y*p2.y + w.x*p3.y;
        r.y = a / (1.f + __expf(-a));
    }
    {
        float4 w = cw4[d0+2];
        float a = bias.z + w.w*cur.z + w.z*p1.z + w.y*p2.z + w.x*p3.z;
        r.z = a / (1.f + __expf(-a));
    }
    {
        float4 w = cw4[d0+3];
        float a = bias.w + w.w*cur.w + w.z*p1.w + w.y*p2.w + w.x*p3.w;
        r.w = a / (1.f + __expf(-a));
    }
    ((float4*)g_xc)[i] = r;
}

// ============================================================================
// K4: x_proj B/C (32 outs) + dt-rank dots for 32-token tiles (grid 512)
// ============================================================================
__global__ __launch_bounds__(256) void k4_xproj(const float* __restrict__ xpw)
{
    __shared__ __align__(16) float sxc[32][132];  // xc tile
    __shared__ __align__(16) float sw4[36][132];  // rows 0..31 = B/C, 32..35 = rank
    __shared__ float sdtr[32][8];

    int m0 = blockIdx.x * 32;
    int tid = threadIdx.x;

    // fill weights (float4)
    for (int i = tid; i < 1152; i += 256) {
        int r = i >> 5, k4i = i & 31;
        const float* src = (r < 32) ? (xpw + (4+r)*128) : (xpw + (r-32)*128);
        float4 v = ((const float4*)src)[k4i];
        *(float4*)&sw4[r][k4i*4] = v;
    }
    // fill activations (float4)
    for (int i = tid; i < 1024; i += 256) {
        int t = i >> 5, k4i = i & 31;
        float4 v = ((const float4*)(g_xc + (m0+t)*128))[k4i];
        *(float4*)&sxc[t][k4i*4] = v;
    }
    __syncthreads();

    // B/C gemm: thread = (o 0..31, tg 0..7) -> tokens tg*4..tg*4+3
    int o  = tid & 31;
    int tg = tid >> 5;
    float acc[4] = {0.f, 0.f, 0.f, 0.f};
    #pragma unroll 8
    for (int k4i = 0; k4i < 32; k4i++) {
        float4 w = *(const float4*)&sw4[o][k4i*4];
        #pragma unroll
        for (int j = 0; j < 4; j++) {
            float4 a = *(const float4*)&sxc[tg*4+j][k4i*4];
            acc[j] += a.x*w.x + a.y*w.y + a.z*w.z + a.w*w.w;
        }
    }
    #pragma unroll
    for (int j = 0; j < 4; j++) {
        int m = m0 + tg*4 + j;
        if (o < 16) g_Bm[m*16 + o]      = acc[j];
        else        g_Cm[m*16 + o - 16] = acc[j];
    }

    // rank dots: thread = (t 0..31, r 0..3, half 0..1)
    {
        int t = tid >> 3;
        int rh = tid & 7;
        int r = rh & 3, hf = rh >> 2;
        float a = 0.f;
        #pragma unroll 8
        for (int k4i = hf*16; k4i < hf*16+16; k4i++) {
            float4 w = *(const float4*)&sw4[32+r][k4i*4];
            float4 xv = *(const float4*)&sxc[t][k4i*4];
            a += xv.x*w.x + xv.y*w.y + xv.z*w.z + xv.w*w.w;
        }
        sdtr[t][rh] = a;
    }
    __syncthreads();
    if (tid < 128) {
        int t = tid >> 2, r = tid & 3;
        g_dtr[(m0+t)*4 + r] = sdtr[t][r] + sdtr[t][r+4];
    }
}

// ============================================================================
// K4b: dt_proj + softplus, fully parallel elementwise
// ============================================================================
__global__ __launch_bounds__(256) void k4b_dt(
    const float* __restrict__ dtw,   // [128][4]
    const float* __restrict__ dtb)   // [128]
{
    int i = blockIdx.x*256 + threadIdx.x;   // over NTOK*DI
    int d = i & 127;
    int m = i >> 7;
    float4 w = ((const float4*)dtw)[d];
    float4 r = ((const float4*)g_dtr)[m];
    float a = dtb[d] + r.x*w.x + r.y*w.y + r.z*w.z + r.w*w.w;
    g_dt[i] = (a > 20.f) ? a : __logf(1.f + __expf(a));
}

// ============================================================================
// K5 (phase A): per-chunk local scan -> h_end, sum(dt)
// warp = (b, chunk, d-pair); lane = s + 16*(d&1)
// ============================================================================
__global__ __launch_bounds__(256) void k5_scanA(const float* __restrict__ A_log)
{
    int warp = (blockIdx.x * 256 + threadIdx.x) >> 5;
    int lane = threadIdx.x & 31;
    int dpair = warp & 63;
    int chunk = (warp >> 6) & (NCHUNK-1);
    int b = warp >> 11;
    int d = dpair*2 + (lane >> 4);
    int s = lane & 15;
    float A = -__expf(A_log[d*16 + s]);
    float h = 0.f, sdt = 0.f;
    int mbase = b*LL + chunk*CSIZE;
    const float* dtp = g_dt + mbase*128 + d;
    const float* xcp = g_xc + mbase*128 + d;
    const float* bp  = g_Bm + mbase*16 + s;
    #pragma unroll 4
    for (int t = 0; t < CSIZE; t++) {
        float dtv = dtp[t*128];
        float xcv = xcp[t*128];
        float bv  = bp[t*16];
        float dA = __expf(dtv * A);
        h = h*dA + dtv*bv*xcv;
        sdt += dtv;
    }
    int ci = (b*NCHUNK + chunk)*128 + d;
    g_hend[ci*16 + s] = h;
    if (s == 0) g_sumdt[ci] = sdt;
}

// ============================================================================
// K6 (phase B): carry scan over chunks
// ============================================================================
__global__ __launch_bounds__(256) void k6_carry(const float* __restrict__ A_log)
{
    int i = blockIdx.x*256 + threadIdx.x;     // 8192 channels
    int s = i & 15;
    int d = (i >> 4) & 127;
    int b = i >> 11;
    float A = -__expf(A_log[d*16+s]);
    float hi = 0.f;
    const float* sump = g_sumdt + b*NCHUNK*128 + d;
    const float* hep  = g_hend  + (b*NCHUNK*128 + d)*16 + s;
    float* hip        = g_hinit + (b*NCHUNK*128 + d)*16 + s;
    #pragma unroll 4
    for (int k = 0; k < NCHUNK; k++) {
        hip[k*128*16] = hi;
        hi = hi*__expf(A * sump[k*128]) + hep[k*128*16];
    }
}

// ============================================================================
// K7 (phase C): replay chunk from h_init, emit ys (transposed [b,d,l])
// ============================================================================
__global__ __launch_bounds__(256) void k7_scanC(
    const float* __restrict__ A_log, const float* __restrict__ Dp)
{
    int warp = (blockIdx.x * 256 + threadIdx.x) >> 5;
    int lane = threadIdx.x & 31;
    int dpair = warp & 63;
    int chunk = (warp >> 6) & (NCHUNK-1);
    int b = warp >> 11;
    int d = dpair*2 + (lane >> 4);
    int s = lane & 15;
    float A = -__expf(A_log[d*16+s]);
    int ci = (b*NCHUNK + chunk)*128 + d;
    float h = g_hinit[ci*16 + s];
    float Dv = Dp[d];
    int mbase = b*LL + chunk*CSIZE;
    const float* dtp = g_dt + mbase*128 + d;
    const float* xcp = g_xc + mbase*128 + d;
    const float* zp  = g_z  + mbase*128 + d;
    const float* bp  = g_Bm + mbase*16 + s;
    const float* cp  = g_Cm + mbase*16 + s;
    float* ysp = g_ysT + (b*128 + d)*LL + chunk*CSIZE;
    #pragma unroll 2
    for (int t = 0; t < CSIZE; t++) {
        float dtv = dtp[t*128];
        float xcv = xcp[t*128];
        float bv = bp[t*16];
        float cv = cp[t*16];
        float dA = __expf(dtv*A);
        h = h*dA + dtv*bv*xcv;
        float p = h * cv;
        p += __shfl_xor_sync(0xffffffffu, p, 8, 16);
        p += __shfl_xor_sync(0xffffffffu, p, 4, 16);
        p += __shfl_xor_sync(0xffffffffu, p, 2, 16);
        p += __shfl_xor_sync(0xffffffffu, p, 1, 16);
        if (s == 0) {
            float zv = zp[t*128];
            float sg = 1.f/(1.f + __expf(-zv));
            ysp[t] = (p + xcv*Dv) * (zv*sg);
        }
    }
}

// ============================================================================
// K8: out_proj GEMM via fma.rn.f32x2 + residual + NCHW write
// Tile 64 tok x 64 chan; thread = (t0 0..15, c0 0..15); token pairs {u,u+32}
// ============================================================================
__global__ __launch_bounds__(256) void k8_outproj(
    const float* __restrict__ Wo, float* __restrict__ out)
{
    __shared__ unsigned long long sy2[32*65];  // [pair u][k] = (ys[u], ys[u+32])
    __shared__ float sw[64][65];               // weight tile [c][k]
    int m0 = blockIdx.x * 64;
    int b = m0 >> 12;
    int l0 = m0 & (LL-1);
    int tid = threadIdx.x;
    int t0 = tid & 15;
    int c0 = tid >> 4;

    unsigned long long acc2[2][4];
    #pragma unroll
    for (int a = 0; a < 2; a++)
        #pragma unroll
        for (int bb = 0; bb < 4; bb++) acc2[a][bb] = 0ULL;

    for (int kb = 0; kb < 2; kb++) {
        if (kb) __syncthreads();
        for (int i = tid; i < 2048; i += 256) {
            int kk = i >> 5, u = i & 31;
            const float* base = g_ysT + (b*128 + kb*64 + kk)*LL + l0;
            sy2[u*65 + kk] = pk2(base[u], base[u+32]);
        }
        for (int i = tid; i < 4096; i += 256) {
            int r = i >> 6, kk = i & 63;
            sw[r][kk] = Wo[r*128 + kb*64 + kk];
        }
        __syncthreads();
        #pragma unroll 4
        for (int k = 0; k < 64; k++) {
            unsigned long long av0 = sy2[t0*65 + k];
            unsigned long long av1 = sy2[(t0+16)*65 + k];
            #pragma unroll
            for (int bb = 0; bb < 4; bb++) {
                float w = sw[c0 + 16*bb][k];
                unsigned long long w2 = pk2(w, w);
                acc2[0][bb] = fma2(av0, w2, acc2[0][bb]);
                acc2[1][bb] = fma2(av1, w2, acc2[1][bb]);
            }
        }
    }

    #pragma unroll
    for (int a = 0; a < 2; a++) {
        int llo = l0 + t0 + 16*a;          // pair = {llo, llo+32}
        #pragma unroll
        for (int bb = 0; bb < 4; bb++) {
            float lo, hi; upk2(acc2[a][bb], lo, hi);
            int cc = c0 + 16*bb;
            int i0 = (b*64 + cc)*LL + llo;
            out[i0]      = lo + g_seqT[i0];
            out[i0 + 32] = hi + g_seqT[i0 + 32];
        }
    }
}

// ============================================================================
extern "C" void kernel_launch(void* const* d_in, const int* in_sizes, int n_in,
                              void* d_out, int out_size)
{
    const float* x        = (const float*)d_in[0];
    const float* dwh_w    = (const float*)d_in[1];
    const float* dwh_b    = (const float*)d_in[2];
    const float* dww_w    = (const float*)d_in[3];
    const float* dww_b    = (const float*)d_in[4];
    const float* conv_w   = (const float*)d_in[5];
    const float* conv_b   = (const float*)d_in[6];
    const float* bn_g     = (const float*)d_in[7];
    const float* bn_b     = (const float*)d_in[8];
    const float* bn_m     = (const float*)d_in[9];
    const float* bn_v     = (const float*)d_in[10];
    const float* ln_g     = (const float*)d_in[11];
    const float* ln_b     = (const float*)d_in[12];
    const float* in_proj_w= (const float*)d_in[13];
    const float* convd_w  = (const float*)d_in[14];
    const float* convd_b  = (const float*)d_in[15];
    const float* x_proj_w = (const float*)d_in[16];
    const float* dt_proj_w= (const float*)d_in[17];
    const float* dt_proj_b= (const float*)d_in[18];
    const float* A_log    = (const float*)d_in[19];
    const float* Dp       = (const float*)d_in[20];
    const float* out_proj_w=(const float*)d_in[21];
    float* out = (float*)d_out;

    k1_front<<<BB*64, 512>>>(x, dwh_w, dwh_b, dww_w, dww_b, conv_w, conv_b,
                             bn_g, bn_b, bn_m, bn_v, ln_g, ln_b);
    k2_inproj<<<dim3(NTOK/64, 4), 256>>>(in_proj_w);
    k3_conv1d<<<(NTOK*32)/256, 256>>>(convd_w, convd_b);
    k4_xproj<<<NTOK/32, 256>>>(x_proj_w);
    k4b_dt<<<(NTOK*DI)/256, 256>>>(dt_proj_w, dt_proj_b);
    k5_scanA<<<(BB*NCHUNK*(DI/2)*32)/256, 256>>>(A_log);
    k6_carry<<<(BB*DI*DS)/256, 256>>>(A_log);
    k7_scanC<<<(BB*NCHUNK*(DI/2)*32)/256, 256>>>(A_log, Dp);
    k8_outproj<<<NTOK/64, 256>>>(out_proj_w, out);
}

// round 11
// speedup vs baseline: 1.5045x; 1.5045x over previous
#include <cuda_runtime.h>
#include <cuda_bf16.h>

// Problem constants
#define CC      64      // channels
#define DI      128     // d_inner
#define DS      16      // d_state
#define LL      4096    // sequence length H*W
#define BB      4       // batch
#define NTOK    (BB*LL) // 16384 tokens
#define NCHUNK  64
#define CSIZE   64      // LL / NCHUNK

// ---------------- scratch (device globals; no allocation allowed) ------------
__device__ __align__(16) float g_hn   [NTOK*CC];   // LayerNorm output [m, c]
__device__ __align__(16) float g_seqT [BB*CC*LL];  // pre-LN activations [b,c,l]
__device__ __align__(16) float g_xm   [NTOK*DI];   // in_proj first half [m, d]
__device__ __align__(16) float g_z    [NTOK*DI];   // in_proj second half [m, d]
__device__ __align__(16) float g_xc   [NTOK*DI];   // conv1d+silu output [m, d]
__device__ __align__(16) float g_dt   [NTOK*DI];   // softplus(dt) [m, d]
__device__ __align__(16) float g_Bm   [NTOK*DS];   // [m, s]
__device__ __align__(16) float g_Cm   [NTOK*DS];   // [m, s]
__device__ __align__(16) float g_dtr  [NTOK*4];    // dt-rank dots [m, r]
__device__ __align__(16) float g_ysT  [BB*DI*LL];  // scan output [b,d,l]
__device__ __align__(16) float g_hend [BB*NCHUNK*DI*DS];
__device__ __align__(16) float g_hinit[BB*NCHUNK*DI*DS];
__device__ __align__(16) float g_sumdt[BB*NCHUNK*DI];

// ============================================================================
// K1: axial depthwise convs + 1x1 conv + BN + ReLU + LayerNorm
// one block per (b, h) image row; 512 threads
// ============================================================================
__global__ __launch_bounds__(512) void k1_front(
    const float* __restrict__ x,
    const float* __restrict__ dwh_w, const float* __restrict__ dwh_b,
    const float* __restrict__ dww_w, const float* __restrict__ dww_b,
    const float* __restrict__ conv_w, const float* __restrict__ conv_b,
    const float* __restrict__ bn_g, const float* __restrict__ bn_b,
    const float* __restrict__ bn_m, const float* __restrict__ bn_v,
    const float* __restrict__ ln_g, const float* __restrict__ ln_b)
{
    __shared__ float sm[64][65];       // m[c][w], later t[c][w]
    __shared__ float scw[64*64];       // 1x1 conv weights
    __shared__ float red_s[64][8];
    __shared__ float red_q[64][8];
    __shared__ float s_mu[64], s_rs[64];

    int bh = blockIdx.x;               // 0..255
    int b = bh >> 6, h = bh & 63;
    int tid = threadIdx.x;

    for (int i = tid; i < 4096; i += 512) scw[i] = conv_w[i];

    for (int i = tid; i < 4096; i += 512) {
        int c = i >> 6, w = i & 63;
        const float* xb = x + ((b*64 + c)*64)*64;
        float center = xb[h*64 + w];
        float acc = center;
        float wh0 = dwh_w[c*3+0], wh1 = dwh_w[c*3+1], wh2 = dwh_w[c*3+2];
        if (h > 0)  acc += wh0 * xb[(h-1)*64 + w];
        acc += wh1 * center;
        if (h < 63) acc += wh2 * xb[(h+1)*64 + w];
        float ww0 = dww_w[c*3+0], ww1 = dww_w[c*3+1], ww2 = dww_w[c*3+2];
        if (w > 0)  acc += ww0 * xb[h*64 + w - 1];
        acc += ww1 * center;
        if (w < 63) acc += ww2 * xb[h*64 + w + 1];
        acc += dwh_b[c] + dww_b[c];
        sm[c][w] = acc;
    }
    __syncthreads();

    float t[8];
    #pragma unroll
    for (int j = 0; j < 8; j++) {
        int i = tid + j*512;
        int o = i >> 6, w = i & 63;
        float acc = 0.f;
        #pragma unroll 8
        for (int c = 0; c < 64; c++) acc += scw[o*64+c]*sm[c][w];
        acc += conv_b[o];
        float rs = rsqrtf(bn_v[o] + 1e-5f);
        acc = (acc - bn_m[o]) * rs * bn_g[o] + bn_b[o];
        t[j] = fmaxf(acc, 0.f);
    }
    __syncthreads();
    #pragma unroll
    for (int j = 0; j < 8; j++) {
        int i = tid + j*512;
        sm[i>>6][i&63] = t[j];
    }
    __syncthreads();

    {
        int w = tid & 63, p = tid >> 6;       // p in 0..7
        float s = 0.f, q = 0.f;
        #pragma unroll
        for (int c = p*8; c < p*8+8; c++) { float v = sm[c][w]; s += v; q += v*v; }
        red_s[w][p] = s; red_q[w][p] = q;
    }
    __syncthreads();
    if (tid < 64) {
        float s = 0.f, q = 0.f;
        #pragma unroll
        for (int p = 0; p < 8; p++) { s += red_s[tid][p]; q += red_q[tid][p]; }
        float mu = s * (1.f/64.f);
        float var = q * (1.f/64.f) - mu*mu;
        s_mu[tid] = mu;
        s_rs[tid] = rsqrtf(var + 1e-5f);
    }
    __syncthreads();

    int mbase = b*LL + h*64;
    for (int i = tid; i < 4096; i += 512) {
        int w = i >> 6, c = i & 63;
        float v = sm[c][w];
        g_hn[(mbase + w)*64 + c] = (v - s_mu[w]) * s_rs[w] * ln_g[c] + ln_b[c];
    }
    for (int i = tid; i < 4096; i += 512) {
        int c = i >> 6, w = i & 63;
        g_seqT[(b*64 + c)*LL + h*64 + w] = sm[c][w];
    }
}

// ============================================================================
// K2: in_proj GEMM  xz[m, 0..255] = hn[m, :] @ W^T ; split into xm / z
// block tile: 64 tokens x 64 outputs; 4x4 register blocking per thread
// (Round-3 proven version)
// ============================================================================
__global__ __launch_bounds__(256) void k2_inproj(const float* __restrict__ W)
{
    __shared__ float sa[64][65];   // hn tile [token][k]
    __shared__ float sw[64][65];   // weight tile [o][k]
    int m0 = blockIdx.x * 64;
    int n0 = blockIdx.y * 64;
    int tid = threadIdx.x;
    for (int i = tid; i < 4096; i += 256) {
        int r = i >> 6, kk = i & 63;
        sa[r][kk] = g_hn[(m0+r)*64 + kk];
        sw[r][kk] = W[(n0+r)*64 + kk];
    }
    __syncthreads();

    int o0 = tid & 15;
    int t0 = tid >> 4;
    float acc[4][4];
    #pragma unroll
    for (int a = 0; a < 4; a++)
        #pragma unroll
        for (int bb = 0; bb < 4; bb++) acc[a][bb] = 0.f;

    #pragma unroll 4
    for (int k = 0; k < 64; k++) {
        float av[4], wv[4];
        #pragma unroll
        for (int a = 0; a < 4; a++)  av[a] = sa[t0 + 16*a][k];
        #pragma unroll
        for (int bb = 0; bb < 4; bb++) wv[bb] = sw[o0 + 16*bb][k];
        #pragma unroll
        for (int a = 0; a < 4; a++)
            #pragma unroll
            for (int bb = 0; bb < 4; bb++) acc[a][bb] += av[a]*wv[bb];
    }

    #pragma unroll
    for (int a = 0; a < 4; a++) {
        int m = m0 + t0 + 16*a;
        #pragma unroll
        for (int bb = 0; bb < 4; bb++) {
            int og = n0 + o0 + 16*bb;
            if (og < 128) g_xm[m*128 + og]       = acc[a][bb];
            else          g_z [m*128 + og - 128] = acc[a][bb];
        }
    }
}

// ============================================================================
// K3: causal depthwise conv1d (k=4) + SiLU, float4 over d
// ============================================================================
__global__ __launch_bounds__(256) void k3_conv1d(
    const float* __restrict__ cw, const float* __restrict__ cb)
{
    int i = blockIdx.x*256 + threadIdx.x;      // over NTOK*32 float4s
    int q = i & 31;            // float4 index within 128 channels
    int m = i >> 5;
    int l = m & (LL-1);
    const float4* xm4 = (const float4*)g_xm;
    const float4* cw4 = (const float4*)cw;     // cw4[d] = 4 taps of channel d
    const float4* cb4 = (const float4*)cb;
    float4 zero = make_float4(0.f,0.f,0.f,0.f);
    float4 cur = xm4[i];
    float4 p1 = (l >= 1) ? xm4[i-32] : zero;
    float4 p2 = (l >= 2) ? xm4[i-64] : zero;
    float4 p3 = (l >= 3) ? xm4[i-96] : zero;
    float4 bias = cb4[q];
    int d0 = q*4;
    float4 r;
    {
        float4 w = cw4[d0+0];
        float a = bias.x + w.w*cur.x + w.z*p1.x + w.y*p2.x + w.x*p3.x;
        r.x = a / (1.f + __expf(-a));
    }
    {
        float4 w = cw4[d0+1];
        float a = bias.y + w.w*cur.y + w.z*p1.y + w.y*p2.y + w.x*p3.y;
        r.y = a / (1.f + __expf(-a));
    }
    {
        float4 w = cw4[d0+2];
        float a = bias.z + w.w*cur.z + w.z*p1.z + w.y*p2.z + w.x*p3.z;
        r.z = a / (1.f + __expf(-a));
    }
    {
        float4 w = cw4[d0+3];
        float a = bias.w + w.w*cur.w + w.z*p1.w + w.y*p2.w + w.x*p3.w;
        r.w = a / (1.f + __expf(-a));
    }
    ((float4*)g_xc)[i] = r;
}

// ============================================================================
// K4: x_proj B/C (32 outs) + dt-rank dots for 32-token tiles (grid 512)
// ============================================================================
__global__ __launch_bounds__(256) void k4_xproj(const float* __restrict__ xpw)
{
    __shared__ __align__(16) float sxc[32][132];  // xc tile
    __shared__ __align__(16) float sw4[36][132];  // rows 0..31 = B/C, 32..35 = rank
    __shared__ float sdtr[32][8];

    int m0 = blockIdx.x * 32;
    int tid = threadIdx.x;

    // fill weights (float4)
    for (int i = tid; i < 1152; i += 256) {
        int r = i >> 5, k4i = i & 31;
        const float* src = (r < 32) ? (xpw + (4+r)*128) : (xpw + (r-32)*128);
        float4 v = ((const float4*)src)[k4i];
        *(float4*)&sw4[r][k4i*4] = v;
    }
    // fill activations (float4)
    for (int i = tid; i < 1024; i += 256) {
        int t = i >> 5, k4i = i & 31;
        float4 v = ((const float4*)(g_xc + (m0+t)*128))[k4i];
        *(float4*)&sxc[t][k4i*4] = v;
    }
    __syncthreads();

    // B/C gemm: thread = (o 0..31, tg 0..7) -> tokens tg*4..tg*4+3
    int o  = tid & 31;
    int tg = tid >> 5;
    float acc[4] = {0.f, 0.f, 0.f, 0.f};
    #pragma unroll 8
    for (int k4i = 0; k4i < 32; k4i++) {
        float4 w = *(const float4*)&sw4[o][k4i*4];
        #pragma unroll
        for (int j = 0; j < 4; j++) {
            float4 a = *(const float4*)&sxc[tg*4+j][k4i*4];
            acc[j] += a.x*w.x + a.y*w.y + a.z*w.z + a.w*w.w;
        }
    }
    #pragma unroll
    for (int j = 0; j < 4; j++) {
        int m = m0 + tg*4 + j;
        if (o < 16) g_Bm[m*16 + o]      = acc[j];
        else        g_Cm[m*16 + o - 16] = acc[j];
    }

    // rank dots: thread = (t 0..31, r 0..3, half 0..1)
    {
        int t = tid >> 3;
        int rh = tid & 7;
        int r = rh & 3, hf = rh >> 2;
        float a = 0.f;
        #pragma unroll 8
        for (int k4i = hf*16; k4i < hf*16+16; k4i++) {
            float4 w = *(const float4*)&sw4[32+r][k4i*4];
            float4 xv = *(const float4*)&sxc[t][k4i*4];
            a += xv.x*w.x + xv.y*w.y + xv.z*w.z + xv.w*w.w;
        }
        sdtr[t][rh] = a;
    }
    __syncthreads();
    if (tid < 128) {
        int t = tid >> 2, r = tid & 3;
        g_dtr[(m0+t)*4 + r] = sdtr[t][r] + sdtr[t][r+4];
    }
}

// ============================================================================
// K4b: dt_proj + softplus, fully parallel elementwise
// ============================================================================
__global__ __launch_bounds__(256) void k4b_dt(
    const float* __restrict__ dtw,   // [128][4]
    const float* __restrict__ dtb)   // [128]
{
    int i = blockIdx.x*256 + threadIdx.x;   // over NTOK*DI
    int d = i & 127;
    int m = i >> 7;
    float4 w = ((const float4*)dtw)[d];
    float4 r = ((const float4*)g_dtr)[m];
    float a = dtb[d] + r.x*w.x + r.y*w.y + r.z*w.z + r.w*w.w;
    g_dt[i] = (a > 20.f) ? a : __logf(1.f + __expf(a));
}

// ============================================================================
// K5 (phase A): per-chunk local scan -> h_end, sum(dt)   (NCHUNK=64 config)
// warp = (b, chunk, d-pair); lane = s + 16*(d&1)
// ============================================================================
__global__ __launch_bounds__(256) void k5_scanA(const float* __restrict__ A_log)
{
    int warp = (blockIdx.x * 256 + threadIdx.x) >> 5;
    int lane = threadIdx.x & 31;
    int dpair = warp & 63;
    int chunk = (warp >> 6) & (NCHUNK-1);
    int b = warp >> 12;
    int d = dpair*2 + (lane >> 4);
    int s = lane & 15;
    float A = -__expf(A_log[d*16 + s]);
    float h = 0.f, sdt = 0.f;
    int mbase = b*LL + chunk*CSIZE;
    const float* dtp = g_dt + mbase*128 + d;
    const float* xcp = g_xc + mbase*128 + d;
    const float* bp  = g_Bm + mbase*16 + s;
    #pragma unroll 4
    for (int t = 0; t < CSIZE; t++) {
        float dtv = dtp[t*128];
        float xcv = xcp[t*128];
        float bv  = bp[t*16];
        float dA = __expf(dtv * A);
        h = h*dA + dtv*bv*xcv;
        sdt += dtv;
    }
    int ci = (b*NCHUNK + chunk)*128 + d;
    g_hend[ci*16 + s] = h;
    if (s == 0) g_sumdt[ci] = sdt;
}

// ============================================================================
// K6 (phase B): carry scan over chunks
// ============================================================================
__global__ __launch_bounds__(256) void k6_carry(const float* __restrict__ A_log)
{
    int i = blockIdx.x*256 + threadIdx.x;     // 8192 channels
    int s = i & 15;
    int d = (i >> 4) & 127;
    int b = i >> 11;
    float A = -__expf(A_log[d*16+s]);
    float hi = 0.f;
    const float* sump = g_sumdt + b*NCHUNK*128 + d;
    const float* hep  = g_hend  + (b*NCHUNK*128 + d)*16 + s;
    float* hip        = g_hinit + (b*NCHUNK*128 + d)*16 + s;
    #pragma unroll 4
    for (int k = 0; k < NCHUNK; k++) {
        hip[k*128*16] = hi;
        hi = hi*__expf(A * sump[k*128]) + hep[k*128*16];
    }
}

// ============================================================================
// K7 (phase C): replay chunk from h_init, emit ys (transposed [b,d,l])
// ============================================================================
__global__ __launch_bounds__(256) void k7_scanC(
    const float* __restrict__ A_log, const float* __restrict__ Dp)
{
    int warp = (blockIdx.x * 256 + threadIdx.x) >> 5;
    int lane = threadIdx.x & 31;
    int dpair = warp & 63;
    int chunk = (warp >> 6) & (NCHUNK-1);
    int b = warp >> 12;
    int d = dpair*2 + (lane >> 4);
    int s = lane & 15;
    float A = -__expf(A_log[d*16+s]);
    int ci = (b*NCHUNK + chunk)*128 + d;
    float h = g_hinit[ci*16 + s];
    float Dv = Dp[d];
    int mbase = b*LL + chunk*CSIZE;
    const float* dtp = g_dt + mbase*128 + d;
    const float* xcp = g_xc + mbase*128 + d;
    const float* zp  = g_z  + mbase*128 + d;
    const float* bp  = g_Bm + mbase*16 + s;
    const float* cp  = g_Cm + mbase*16 + s;
    float* ysp = g_ysT + (b*128 + d)*LL + chunk*CSIZE;
    #pragma unroll 2
    for (int t = 0; t < CSIZE; t++) {
        float dtv = dtp[t*128];
        float xcv = xcp[t*128];
        float bv = bp[t*16];
        float cv = cp[t*16];
        float dA = __expf(dtv*A);
        h = h*dA + dtv*bv*xcv;
        float p = h * cv;
        p += __shfl_xor_sync(0xffffffffu, p, 8, 16);
        p += __shfl_xor_sync(0xffffffffu, p, 4, 16);
        p += __shfl_xor_sync(0xffffffffu, p, 2, 16);
        p += __shfl_xor_sync(0xffffffffu, p, 1, 16);
        if (s == 0) {
            float zv = zp[t*128];
            float sg = 1.f/(1.f + __expf(-zv));
            ysp[t] = (p + xcv*Dv) * (zv*sg);
        }
    }
}

// ============================================================================
// K8: out_proj GEMM (K=128, two 64-k blocks) + residual + NCHW write
// block = 64 tokens x 64 channels; 4x4 register blocking (Round-3 proven)
// ============================================================================
__global__ __launch_bounds__(256) void k8_outproj(
    const float* __restrict__ Wo, float* __restrict__ out)
{
    __shared__ float sy[64][65];   // ys tile [token][k]
    __shared__ float sw[64][65];   // weight tile [c][k]
    int m0 = blockIdx.x * 64;
    int b = m0 >> 12;
    int l0 = m0 & (LL-1);
    int tid = threadIdx.x;
    int t0 = tid & 15;    // token (lane-consecutive) + 16*a
    int c0 = tid >> 4;    // channel + 16*bb

    float acc[4][4];
    #pragma unroll
    for (int a = 0; a < 4; a++)
        #pragma unroll
        for (int bb = 0; bb < 4; bb++) acc[a][bb] = 0.f;

    for (int kb = 0; kb < 2; kb++) {
        if (kb) __syncthreads();
        for (int i = tid; i < 4096; i += 256) {
            int kk = i >> 6, r = i & 63;     // r fastest -> coalesced ysT load
            sy[r][kk] = g_ysT[(b*128 + kb*64 + kk)*LL + l0 + r];
        }
        for (int i = tid; i < 4096; i += 256) {
            int r = i >> 6, kk = i & 63;
            sw[r][kk] = Wo[r*128 + kb*64 + kk];
        }
        __syncthreads();
        #pragma unroll 4
        for (int k = 0; k < 64; k++) {
            float av[4], wv[4];
            #pragma unroll
            for (int a = 0; a < 4; a++)  av[a] = sy[t0 + 16*a][k];
            #pragma unroll
            for (int bb = 0; bb < 4; bb++) wv[bb] = sw[c0 + 16*bb][k];
            #pragma unroll
            for (int a = 0; a < 4; a++)
                #pragma unroll
                for (int bb = 0; bb < 4; bb++) acc[a][bb] += av[a]*wv[bb];
        }
    }

    #pragma unroll
    for (int a = 0; a < 4; a++) {
        int l = l0 + t0 + 16*a;
        #pragma unroll
        for (int bb = 0; bb < 4; bb++) {
            int cc = c0 + 16*bb;
            int idx = (b*64 + cc)*LL + l;
            out[idx] = acc[a][bb] + g_seqT[idx];
        }
    }
}

// ============================================================================
extern "C" void kernel_launch(void* const* d_in, const int* in_sizes, int n_in,
                              void* d_out, int out_size)
{
    const float* x        = (const float*)d_in[0];
    const float* dwh_w    = (const float*)d_in[1];
    const float* dwh_b    = (const float*)d_in[2];
    const float* dww_w    = (const float*)d_in[3];
    const float* dww_b    = (const float*)d_in[4];
    const float* conv_w   = (const float*)d_in[5];
    const float* conv_b   = (const float*)d_in[6];
    const float* bn_g     = (const float*)d_in[7];
    const float* bn_b     = (const float*)d_in[8];
    const float* bn_m     = (const float*)d_in[9];
    const float* bn_v     = (const float*)d_in[10];
    const float* ln_g     = (const float*)d_in[11];
    const float* ln_b     = (const float*)d_in[12];
    const float* in_proj_w= (const float*)d_in[13];
    const float* convd_w  = (const float*)d_in[14];
    const float* convd_b  = (const float*)d_in[15];
    const float* x_proj_w = (const float*)d_in[16];
    const float* dt_proj_w= (const float*)d_in[17];
    const float* dt_proj_b= (const float*)d_in[18];
    const float* A_log    = (const float*)d_in[19];
    const float* Dp       = (const float*)d_in[20];
    const float* out_proj_w=(const float*)d_in[21];
    float* out = (float*)d_out;

    k1_front<<<BB*64, 512>>>(x, dwh_w, dwh_b, dww_w, dww_b, conv_w, conv_b,
                             bn_g, bn_b, bn_m, bn_v, ln_g, ln_b);
    k2_inproj<<<dim3(NTOK/64, 4), 256>>>(in_proj_w);
    k3_conv1d<<<(NTOK*32)/256, 256>>>(convd_w, convd_b);
    k4_xproj<<<NTOK/32, 256>>>(x_proj_w);
    k4b_dt<<<(NTOK*DI)/256, 256>>>(dt_proj_w, dt_proj_b);
    k5_scanA<<<(BB*NCHUNK*(DI/2))/8, 256>>>(A_log);
    k6_carry<<<(BB*DI*DS)/256, 256>>>(A_log);
    k7_scanC<<<(BB*NCHUNK*(DI/2))/8, 256>>>(A_log, Dp);
    k8_outproj<<<NTOK/64, 256>>>(out_proj_w, out);
}